// round 3
// baseline (speedup 1.0000x reference)
#include <cuda_runtime.h>
#include <mma.h>
using namespace nvcuda;

#define DIMC   1024
#define HEADS  16
#define HD     64
#define BATCH  512
#define SEQ    65
#define MROWS  (BATCH * SEQ)   // 33280

// Scratch (allocation-free rule: __device__ globals)
__device__ float g_qkv[(size_t)MROWS * 3 * DIMC];  // [B*N, 3*DIM]
__device__ float g_att[(size_t)MROWS * DIMC];      // [B*N, DIM] attention output

// ---------------------------------------------------------------------------
// GEMM: C[M,N] = A[M,K] * B[N,K]^T  (both row-major), tf32 WMMA, fp32 accum
// Block tile 64x64, 4 warps (2x2), warp tile 32x32 (2x2 frags of 16x16x8)
// Requires M%64==0, N%64==0, K%32==0 (true for all our shapes)
// ---------------------------------------------------------------------------
constexpr int BKD = 32;
constexpr int LDT = 36;  // padded smem leading dim (multiple of 4 for tf32 ld)

__global__ void __launch_bounds__(128) gemm_bt(const float* __restrict__ A,
                                               const float* __restrict__ B,
                                               float* __restrict__ C,
                                               int M, int N, int K) {
    __shared__ __align__(16) float As[64 * LDT];
    __shared__ __align__(16) float Bs[64 * LDT];
    const int tid  = threadIdx.x;
    const int warp = tid >> 5;
    const int wm   = warp >> 1, wn = warp & 1;
    const int bm   = blockIdx.y * 64, bn = blockIdx.x * 64;

    wmma::fragment<wmma::accumulator, 16, 16, 8, float> acc[2][2];
#pragma unroll
    for (int i = 0; i < 2; i++)
#pragma unroll
        for (int j = 0; j < 2; j++) wmma::fill_fragment(acc[i][j], 0.0f);

    for (int k0 = 0; k0 < K; k0 += BKD) {
#pragma unroll
        for (int i = tid; i < 64 * 8; i += 128) {
            int r = i >> 3, c = (i & 7) << 2;
            *(float4*)&As[r * LDT + c] =
                *(const float4*)&A[(size_t)(bm + r) * K + k0 + c];
            *(float4*)&Bs[r * LDT + c] =
                *(const float4*)&B[(size_t)(bn + r) * K + k0 + c];
        }
        __syncthreads();
#pragma unroll
        for (int kk = 0; kk < BKD; kk += 8) {
            wmma::fragment<wmma::matrix_a, 16, 16, 8, wmma::precision::tf32,
                           wmma::row_major> af[2];
            wmma::fragment<wmma::matrix_b, 16, 16, 8, wmma::precision::tf32,
                           wmma::col_major> bf[2];
#pragma unroll
            for (int i = 0; i < 2; i++) {
                wmma::load_matrix_sync(af[i], &As[(wm * 32 + i * 16) * LDT + kk], LDT);
#pragma unroll
                for (int t = 0; t < af[i].num_elements; t++)
                    af[i].x[t] = wmma::__float_to_tf32(af[i].x[t]);
                wmma::load_matrix_sync(bf[i], &Bs[(wn * 32 + i * 16) * LDT + kk], LDT);
#pragma unroll
                for (int t = 0; t < bf[i].num_elements; t++)
                    bf[i].x[t] = wmma::__float_to_tf32(bf[i].x[t]);
            }
#pragma unroll
            for (int i = 0; i < 2; i++)
#pragma unroll
                for (int j = 0; j < 2; j++)
                    wmma::mma_sync(acc[i][j], af[i], bf[j], acc[i][j]);
        }
        __syncthreads();
    }
#pragma unroll
    for (int i = 0; i < 2; i++)
#pragma unroll
        for (int j = 0; j < 2; j++)
            wmma::store_matrix_sync(
                &C[(size_t)(bm + wm * 32 + i * 16) * N + bn + wn * 32 + j * 16],
                acc[i][j], N, wmma::mem_row_major);
}

// ---------------------------------------------------------------------------
// Fused attention: one CTA per (b, h). LN(q)*scale, LN(k), S = qk^T + bias,
// softmax, O = P v.  256 threads. All tiles live in smem; 4x4 register tiling
// on both matmuls; K stored transposed for conflict-free float4 loads.
// Padding: logical 65 padded to 68 (zeroed where it matters).
// ---------------------------------------------------------------------------
#define Q_OFF  0              // q:  [68 rows][stride 68], only d<64 used
#define KV_OFF 4624           // kT: [64 d][stride 68, cols=n] then v: [68 m][stride 68]
#define S_OFF  9248           // s:  [68][68]
#define SMEM_ATT (13872 * 4)  // 55488 bytes

__global__ void __launch_bounds__(256) attn_kernel(
    const float* __restrict__ qkv, const float* __restrict__ bias,
    const float* __restrict__ bscale_p,
    const float* __restrict__ qn_w, const float* __restrict__ qn_b,
    const float* __restrict__ kn_w, const float* __restrict__ kn_b,
    float* __restrict__ outp) {
    extern __shared__ float sm[];
    float* q_s  = sm + Q_OFF;
    float* kv_s = sm + KV_OFF;   // holds kT first, then v
    float* s_s  = sm + S_OFF;

    const int tid = threadIdx.x, lane = tid & 31, warp = tid >> 5;
    const int h = blockIdx.x, b = blockIdx.y;
    const float bscale = *bscale_p;
    const size_t base = (size_t)b * SEQ * 3072 + (size_t)h * 64;

    // Phase 1: load q (row-major, padded rows zero) and k (transposed, padded cols zero)
    for (int i = tid; i < 68 * 64; i += 256) {
        int n = i >> 6, d = i & 63;
        float qv = 0.f, kv = 0.f;
        if (n < SEQ) {
            qv = qkv[base + (size_t)n * 3072 + d];
            kv = qkv[base + (size_t)n * 3072 + 1024 + d];
        }
        q_s[n * 68 + d]  = qv;
        kv_s[d * 68 + n] = kv;   // kT[d][n]
    }
    __syncthreads();

    // Phase 2: LayerNorm rows (q scaled by hd^-0.5)
    const float qw0 = qn_w[lane], qw1 = qn_w[lane + 32];
    const float qb0 = qn_b[lane], qb1 = qn_b[lane + 32];
    const float kw0 = kn_w[lane], kw1 = kn_w[lane + 32];
    const float kb0 = kn_b[lane], kb1 = kn_b[lane + 32];
    for (int n = warp; n < SEQ; n += 8) {
        float x0 = q_s[n * 68 + lane], x1 = q_s[n * 68 + lane + 32];
        float s = x0 + x1, sq = x0 * x0 + x1 * x1;
#pragma unroll
        for (int o = 16; o; o >>= 1) {
            s += __shfl_xor_sync(0xffffffffu, s, o);
            sq += __shfl_xor_sync(0xffffffffu, sq, o);
        }
        float mu = s * (1.f / 64.f);
        float rstd = rsqrtf(sq * (1.f / 64.f) - mu * mu + 1e-5f);
        q_s[n * 68 + lane]      = ((x0 - mu) * rstd * qw0 + qb0) * 0.125f;
        q_s[n * 68 + lane + 32] = ((x1 - mu) * rstd * qw1 + qb1) * 0.125f;

        x0 = kv_s[lane * 68 + n]; x1 = kv_s[(lane + 32) * 68 + n];
        s = x0 + x1; sq = x0 * x0 + x1 * x1;
#pragma unroll
        for (int o = 16; o; o >>= 1) {
            s += __shfl_xor_sync(0xffffffffu, s, o);
            sq += __shfl_xor_sync(0xffffffffu, sq, o);
        }
        mu = s * (1.f / 64.f);
        rstd = rsqrtf(sq * (1.f / 64.f) - mu * mu + 1e-5f);
        kv_s[lane * 68 + n]        = (x0 - mu) * rstd * kw0 + kb0;
        kv_s[(lane + 32) * 68 + n] = (x1 - mu) * rstd * kw1 + kb1;
    }
    __syncthreads();

    // Phase 3: S[n][m] = q[n].k[m] + bias, 4x4 register tiles over 17x17 grid
    for (int idx = tid; idx < 17 * 17; idx += 256) {
        int n0 = (idx / 17) * 4, m0 = (idx % 17) * 4;
        float acc[4][4] = {};
#pragma unroll 8
        for (int d = 0; d < 64; d++) {
            float4 kv4 = *(float4*)&kv_s[d * 68 + m0];  // kT row, conflict-free
            float kvv[4] = {kv4.x, kv4.y, kv4.z, kv4.w};
#pragma unroll
            for (int i = 0; i < 4; i++) {
                float qv = q_s[(n0 + i) * 68 + d];
#pragma unroll
                for (int j = 0; j < 4; j++) acc[i][j] = fmaf(qv, kvv[j], acc[i][j]);
            }
        }
#pragma unroll
        for (int i = 0; i < 4; i++)
#pragma unroll
            for (int j = 0; j < 4; j++) {
                int n = n0 + i, m = m0 + j;
                float bv = (n < SEQ && m < SEQ)
                               ? bias[((size_t)h * SEQ + n) * SEQ + m] * bscale
                               : 0.f;
                s_s[n * 68 + m] = acc[i][j] + bv;  // pad rows/cols get 0
            }
    }
    __syncthreads();

    // Phase 4a: load v into kv_s (row-major stride 68, pad rows zeroed)
    for (int i = tid; i < 68 * 64; i += 256) {
        int n = i >> 6, d = i & 63;
        kv_s[n * 68 + d] =
            (n < SEQ) ? qkv[base + (size_t)n * 3072 + 2048 + d] : 0.f;
    }
    // Phase 4b: softmax rows (strictly over m<65), zero pad cols
    for (int n = warp; n < SEQ; n += 8) {
        float v0 = s_s[n * 68 + lane], v1 = s_s[n * 68 + lane + 32];
        float v2 = (lane == 0) ? s_s[n * 68 + 64] : -3.4e38f;
        float mx = fmaxf(fmaxf(v0, v1), v2);
#pragma unroll
        for (int o = 16; o; o >>= 1) mx = fmaxf(mx, __shfl_xor_sync(0xffffffffu, mx, o));
        float e0 = __expf(v0 - mx), e1 = __expf(v1 - mx);
        float e2 = (lane == 0) ? __expf(v2 - mx) : 0.f;
        float sum = e0 + e1 + e2;
#pragma unroll
        for (int o = 16; o; o >>= 1) sum += __shfl_xor_sync(0xffffffffu, sum, o);
        float inv = 1.f / sum;
        s_s[n * 68 + lane]      = e0 * inv;
        s_s[n * 68 + lane + 32] = e1 * inv;
        if (lane == 0) {
            s_s[n * 68 + 64] = e2 * inv;
            s_s[n * 68 + 65] = 0.f; s_s[n * 68 + 66] = 0.f; s_s[n * 68 + 67] = 0.f;
        }
    }
    __syncthreads();

    // Phase 5: O[n][d] = sum_m P[n][m] * V[m][d], 4x4 tiles over 17x16 grid
    for (int idx = tid; idx < 17 * 16; idx += 256) {
        int n0 = (idx / 16) * 4, d0 = (idx % 16) * 4;
        float acc[4][4] = {};
#pragma unroll 4
        for (int m = 0; m < 68; m++) {
            float4 vv4 = *(float4*)&kv_s[m * 68 + d0];  // conflict-free
            float vvv[4] = {vv4.x, vv4.y, vv4.z, vv4.w};
#pragma unroll
            for (int i = 0; i < 4; i++) {
                float pv = s_s[(n0 + i) * 68 + m];
#pragma unroll
                for (int j = 0; j < 4; j++) acc[i][j] = fmaf(pv, vvv[j], acc[i][j]);
            }
        }
#pragma unroll
        for (int i = 0; i < 4; i++) {
            int n = n0 + i;
            if (n < SEQ) {
                size_t o = ((size_t)b * SEQ + n) * DIMC + (size_t)h * 64 + d0;
#pragma unroll
                for (int j = 0; j < 4; j++) outp[o + j] = acc[i][j];
            }
        }
    }
}

// ---------------------------------------------------------------------------
extern "C" void kernel_launch(void* const* d_in, const int* in_sizes, int n_in,
                              void* d_out, int out_size) {
    const float* x      = (const float*)d_in[0];
    const float* w_qkv  = (const float*)d_in[1];
    const float* w_proj = (const float*)d_in[2];
    const float* qn_w   = (const float*)d_in[3];
    const float* qn_b   = (const float*)d_in[4];
    const float* kn_w   = (const float*)d_in[5];
    const float* kn_b   = (const float*)d_in[6];
    const float* bias   = (const float*)d_in[7];
    const float* bscale = (const float*)d_in[8];
    float* out          = (float*)d_out;

    float* qkv_ptr = nullptr;
    float* att_ptr = nullptr;
    cudaGetSymbolAddress((void**)&qkv_ptr, g_qkv);
    cudaGetSymbolAddress((void**)&att_ptr, g_att);

    cudaFuncSetAttribute(attn_kernel, cudaFuncAttributeMaxDynamicSharedMemorySize,
                         SMEM_ATT);

    // 1) QKV projection: [33280,1024] x [3072,1024]^T -> [33280,3072]
    gemm_bt<<<dim3(3 * DIMC / 64, MROWS / 64), 128>>>(x, w_qkv, qkv_ptr,
                                                      MROWS, 3 * DIMC, DIMC);
    // 2) Fused LN + attention per (b,h)
    attn_kernel<<<dim3(HEADS, BATCH), 256, SMEM_ATT>>>(
        qkv_ptr, bias, bscale, qn_w, qn_b, kn_w, kn_b, att_ptr);
    // 3) Output projection: [33280,1024] x [1024,1024]^T -> [33280,1024]
    gemm_bt<<<dim3(DIMC / 64, MROWS / 64), 128>>>(att_ptr, w_proj, out,
                                                  MROWS, DIMC, DIMC);
}